// round 2
// baseline (speedup 1.0000x reference)
#include <cuda_runtime.h>

#define N_NODES 100000
#define N_EDGES 1600000
#define DIN 8
#define H 32
#define SCAN_CHUNK 512
#define FULL 0xffffffffu

// ---------------- scratch (device globals; no allocation allowed) ----------
__device__ int   g_counts[N_NODES];
__device__ int   g_offsets[N_NODES];
__device__ int   g_cursor[N_NODES];
__device__ int   g_blockSums[256];
__device__ int   g_csr[N_EDGES];
__device__ float g_hA[N_NODES * H];
__device__ float g_hB[N_NODES * H];

// ---------------- CSR build -------------------------------------------------
__global__ void k_zero_counts() {
    int i = blockIdx.x * blockDim.x + threadIdx.x;
    if (i < N_NODES) g_counts[i] = 0;
}

__global__ void k_hist(const int* __restrict__ dst) {
    int i = blockIdx.x * blockDim.x + threadIdx.x;
    if (i < N_EDGES) atomicAdd(&g_counts[dst[i]], 1);
}

__global__ void k_scan1() {
    __shared__ int s[SCAN_CHUNK];
    int t = threadIdx.x;
    int base = blockIdx.x * SCAN_CHUNK;
    int v = (base + t < N_NODES) ? g_counts[base + t] : 0;
    s[t] = v;
    __syncthreads();
    for (int d = 1; d < SCAN_CHUNK; d <<= 1) {
        int add = (t >= d) ? s[t - d] : 0;
        __syncthreads();
        s[t] += add;
        __syncthreads();
    }
    if (base + t < N_NODES) g_offsets[base + t] = s[t] - v;  // exclusive within chunk
    if (t == SCAN_CHUNK - 1) g_blockSums[blockIdx.x] = s[t];
}

__global__ void k_scan2(int nblk) {
    __shared__ int s[256];
    int t = threadIdx.x;
    int v = (t < nblk) ? g_blockSums[t] : 0;
    s[t] = v;
    __syncthreads();
    for (int d = 1; d < 256; d <<= 1) {
        int add = (t >= d) ? s[t - d] : 0;
        __syncthreads();
        s[t] += add;
        __syncthreads();
    }
    if (t < nblk) g_blockSums[t] = s[t] - v;  // exclusive block offsets
}

__global__ void k_scan3() {
    int i = blockIdx.x * blockDim.x + threadIdx.x;
    if (i < N_NODES) {
        int v = g_offsets[i] + g_blockSums[i / SCAN_CHUNK];
        g_offsets[i] = v;
        g_cursor[i]  = v;
    }
}

__global__ void k_fill(const int* __restrict__ src,
                       const int* __restrict__ dst) {
    int i = blockIdx.x * blockDim.x + threadIdx.x;
    if (i < N_EDGES) {
        int d = dst[i];
        int p = atomicAdd(&g_cursor[d], 1);
        g_csr[p] = src[i];
    }
}

// ---------------- layer 1: x[N,8] -> g_hA[N,32] -----------------------------
__global__ void __launch_bounds__(256) k_layer1(const float* __restrict__ x,
                                                const float* __restrict__ Wl,
                                                const float* __restrict__ bl,
                                                const float* __restrict__ Wr) {
    __shared__ float Wls[DIN * H], Wrs[DIN * H], bls[H];
    for (int i = threadIdx.x; i < DIN * H; i += blockDim.x) {
        Wls[i] = Wl[i];
        Wrs[i] = Wr[i];
    }
    if (threadIdx.x < H) bls[threadIdx.x] = bl[threadIdx.x];
    __syncthreads();

    int n    = (blockIdx.x * blockDim.x + threadIdx.x) >> 5;
    int lane = threadIdx.x & 31;
    if (n >= N_NODES) return;

    int base = g_offsets[n];
    int cnt  = g_counts[n];

    // 4 edges per iteration: lane = sub*8 + j, j = feature dim (0..7)
    int sub = lane >> 3, j = lane & 7;
    float acc = 0.f;
    for (int i = 0; i < cnt; i += 4) {
        int e = i + sub;
        if (e < cnt) {
            int s = g_csr[base + e];
            acc += x[s * DIN + j];
        }
    }
    acc += __shfl_down_sync(FULL, acc, 16);
    acc += __shfl_down_sync(FULL, acc, 8);   // lanes 0..7 hold totals per dim

    float inv  = 1.f / fmaxf((float)cnt, 1.f);
    float mean = acc * inv;                       // valid in lanes 0..7
    float xv   = (lane < 8) ? x[n * DIN + lane] : 0.f;

    float o = bls[lane];
#pragma unroll
    for (int k = 0; k < DIN; k++) {
        float mk = __shfl_sync(FULL, mean, k);
        float xk = __shfl_sync(FULL, xv, k);
        o += mk * Wls[k * H + lane] + xk * Wrs[k * H + lane];
    }
    g_hA[n * H + lane] = fmaxf(o, 0.f);
}

// ---------------- layer 2: g_hA -> g_hB --------------------------------------
__global__ void __launch_bounds__(256) k_layer2(const float* __restrict__ Wl,
                                                const float* __restrict__ bl,
                                                const float* __restrict__ Wr) {
    __shared__ float Wls[H * H], Wrs[H * H], bls[H];
    for (int i = threadIdx.x; i < H * H; i += blockDim.x) {
        Wls[i] = Wl[i];
        Wrs[i] = Wr[i];
    }
    if (threadIdx.x < H) bls[threadIdx.x] = bl[threadIdx.x];
    __syncthreads();

    int n    = (blockIdx.x * blockDim.x + threadIdx.x) >> 5;
    int lane = threadIdx.x & 31;
    if (n >= N_NODES) return;

    int base = g_offsets[n];
    int cnt  = g_counts[n];

    float acc = 0.f;
    for (int i = 0; i < cnt; i += 32) {
        int e = i + lane;
        int s = (e < cnt) ? g_csr[base + e] : 0;
        int m = cnt - i;
        if (m > 32) m = 32;
        for (int t = 0; t < m; t++) {
            int sj = __shfl_sync(FULL, s, t);
            acc += g_hA[sj * H + lane];          // coalesced 128B row
        }
    }
    float mean = acc / fmaxf((float)cnt, 1.f);
    float hv   = g_hA[n * H + lane];

    float o = bls[lane];
#pragma unroll
    for (int k = 0; k < H; k++) {
        float mk = __shfl_sync(FULL, mean, k);
        float hk = __shfl_sync(FULL, hv, k);
        o += mk * Wls[k * H + lane] + hk * Wrs[k * H + lane];
    }
    g_hB[n * H + lane] = fmaxf(o, 0.f);
}

// ---------------- layer 3 + MLP head: g_hB -> out[N,3] -----------------------
__global__ void __launch_bounds__(256) k_layer3_head(float* __restrict__ out,
                                                     const float* __restrict__ Wl,
                                                     const float* __restrict__ bl,
                                                     const float* __restrict__ Wr,
                                                     const float* __restrict__ Wh1,
                                                     const float* __restrict__ bh1,
                                                     const float* __restrict__ Wh2,
                                                     const float* __restrict__ bh2) {
    __shared__ float Wls[H * H], Wrs[H * H], W1s[H * H], bls[H], b1s[H];
    __shared__ float W2s[H * 3], b2s[3];
    for (int i = threadIdx.x; i < H * H; i += blockDim.x) {
        Wls[i] = Wl[i];
        Wrs[i] = Wr[i];
        W1s[i] = Wh1[i];
    }
    if (threadIdx.x < H) {
        bls[threadIdx.x] = bl[threadIdx.x];
        b1s[threadIdx.x] = bh1[threadIdx.x];
    }
    for (int i = threadIdx.x; i < H * 3; i += blockDim.x) W2s[i] = Wh2[i];
    if (threadIdx.x < 3) b2s[threadIdx.x] = bh2[threadIdx.x];
    __syncthreads();

    int n    = (blockIdx.x * blockDim.x + threadIdx.x) >> 5;
    int lane = threadIdx.x & 31;
    if (n >= N_NODES) return;

    int base = g_offsets[n];
    int cnt  = g_counts[n];

    float acc = 0.f;
    for (int i = 0; i < cnt; i += 32) {
        int e = i + lane;
        int s = (e < cnt) ? g_csr[base + e] : 0;
        int m = cnt - i;
        if (m > 32) m = 32;
        for (int t = 0; t < m; t++) {
            int sj = __shfl_sync(FULL, s, t);
            acc += g_hB[sj * H + lane];
        }
    }
    float mean = acc / fmaxf((float)cnt, 1.f);
    float hv   = g_hB[n * H + lane];

    float o = bls[lane];
#pragma unroll
    for (int k = 0; k < H; k++) {
        float mk = __shfl_sync(FULL, mean, k);
        float hk = __shfl_sync(FULL, hv, k);
        o += mk * Wls[k * H + lane] + hk * Wrs[k * H + lane];
    }
    float h3 = fmaxf(o, 0.f);

    // head layer 1: 32 -> 32, relu
    float t1 = b1s[lane];
#pragma unroll
    for (int k = 0; k < H; k++) {
        float hk = __shfl_sync(FULL, h3, k);
        t1 += hk * W1s[k * H + lane];
    }
    t1 = fmaxf(t1, 0.f);

    // head layer 2: 32 -> 3, warp reduction
    float p0 = t1 * W2s[lane * 3 + 0];
    float p1 = t1 * W2s[lane * 3 + 1];
    float p2 = t1 * W2s[lane * 3 + 2];
#pragma unroll
    for (int off = 16; off > 0; off >>= 1) {
        p0 += __shfl_xor_sync(FULL, p0, off);
        p1 += __shfl_xor_sync(FULL, p1, off);
        p2 += __shfl_xor_sync(FULL, p2, off);
    }
    if (lane == 0) {
        out[n * 3 + 0] = p0 + b2s[0];
        out[n * 3 + 1] = p1 + b2s[1];
        out[n * 3 + 2] = p2 + b2s[2];
    }
}

// ---------------- launcher ---------------------------------------------------
extern "C" void kernel_launch(void* const* d_in, const int* in_sizes, int n_in,
                              void* d_out, int out_size) {
    const float* x   = (const float*)d_in[0];
    const int*   ei  = (const int*)d_in[1];    // int64 in reference -> int32 on device
    const int*   src = ei;
    const int*   dst = ei + N_EDGES;
    const float* Wl1 = (const float*)d_in[2];
    const float* bl1 = (const float*)d_in[3];
    const float* Wr1 = (const float*)d_in[4];
    const float* Wl2 = (const float*)d_in[5];
    const float* bl2 = (const float*)d_in[6];
    const float* Wr2 = (const float*)d_in[7];
    const float* Wl3 = (const float*)d_in[8];
    const float* bl3 = (const float*)d_in[9];
    const float* Wr3 = (const float*)d_in[10];
    const float* Wh1 = (const float*)d_in[11];
    const float* bh1 = (const float*)d_in[12];
    const float* Wh2 = (const float*)d_in[13];
    const float* bh2 = (const float*)d_in[14];
    float* out = (float*)d_out;

    int nblk = (N_NODES + SCAN_CHUNK - 1) / SCAN_CHUNK;

    k_zero_counts<<<(N_NODES + 255) / 256, 256>>>();
    k_hist<<<(N_EDGES + 255) / 256, 256>>>(dst);
    k_scan1<<<nblk, SCAN_CHUNK>>>();
    k_scan2<<<1, 256>>>(nblk);
    k_scan3<<<(N_NODES + 255) / 256, 256>>>();
    k_fill<<<(N_EDGES + 255) / 256, 256>>>(src, dst);

    int node_blocks = (N_NODES + 7) / 8;  // 8 warps (nodes) per 256-thread block
    k_layer1<<<node_blocks, 256>>>(x, Wl1, bl1, Wr1);
    k_layer2<<<node_blocks, 256>>>(Wl2, bl2, Wr2);
    k_layer3_head<<<node_blocks, 256>>>(out, Wl3, bl3, Wr3, Wh1, bh1, Wh2, bh2);
}

// round 3
// speedup vs baseline: 1.0429x; 1.0429x over previous
#include <cuda_runtime.h>

#define N_NODES 100000
#define N_EDGES 1600000
#define DIN 8
#define H 32
#define WPAD 36            // padded transposed-weight row stride (floats)
#define SCAN_CHUNK 512
#define FULL 0xffffffffu

// ---------------- scratch (device globals; no allocation allowed) ----------
__device__ int   g_counts[N_NODES];
__device__ int   g_offsets[N_NODES];
__device__ int   g_cursor[N_NODES];
__device__ int   g_blockSums[256];
__device__ int   g_csr[N_EDGES];
__device__ float g_hA[N_NODES * H];
__device__ float g_hB[N_NODES * H];

// ---------------- CSR build -------------------------------------------------
__global__ void k_zero_counts() {
    int i = blockIdx.x * blockDim.x + threadIdx.x;
    if (i < N_NODES / 4) ((int4*)g_counts)[i] = make_int4(0, 0, 0, 0);
}

__global__ void k_hist(const int* __restrict__ dst) {
    int i = blockIdx.x * blockDim.x + threadIdx.x;
    if (i < N_EDGES / 4) {
        int4 d = ((const int4*)dst)[i];
        atomicAdd(&g_counts[d.x], 1);
        atomicAdd(&g_counts[d.y], 1);
        atomicAdd(&g_counts[d.z], 1);
        atomicAdd(&g_counts[d.w], 1);
    }
}

__global__ void k_scan1() {
    __shared__ int s[SCAN_CHUNK];
    int t = threadIdx.x;
    int base = blockIdx.x * SCAN_CHUNK;
    int v = (base + t < N_NODES) ? g_counts[base + t] : 0;
    s[t] = v;
    __syncthreads();
    for (int d = 1; d < SCAN_CHUNK; d <<= 1) {
        int add = (t >= d) ? s[t - d] : 0;
        __syncthreads();
        s[t] += add;
        __syncthreads();
    }
    if (base + t < N_NODES) g_offsets[base + t] = s[t] - v;  // exclusive within chunk
    if (t == SCAN_CHUNK - 1) g_blockSums[blockIdx.x] = s[t];
}

__global__ void k_scan2(int nblk) {
    __shared__ int s[256];
    int t = threadIdx.x;
    int v = (t < nblk) ? g_blockSums[t] : 0;
    s[t] = v;
    __syncthreads();
    for (int d = 1; d < 256; d <<= 1) {
        int add = (t >= d) ? s[t - d] : 0;
        __syncthreads();
        s[t] += add;
        __syncthreads();
    }
    if (t < nblk) g_blockSums[t] = s[t] - v;  // exclusive block offsets
}

__global__ void k_scan3() {
    int i = blockIdx.x * blockDim.x + threadIdx.x;
    if (i < N_NODES) {
        int v = g_offsets[i] + g_blockSums[i / SCAN_CHUNK];
        g_offsets[i] = v;
        g_cursor[i]  = v;
    }
}

__global__ void k_fill(const int* __restrict__ src,
                       const int* __restrict__ dst) {
    int i = blockIdx.x * blockDim.x + threadIdx.x;
    if (i < N_EDGES / 4) {
        int4 d = ((const int4*)dst)[i];
        int4 s = ((const int4*)src)[i];
        g_csr[atomicAdd(&g_cursor[d.x], 1)] = s.x;
        g_csr[atomicAdd(&g_cursor[d.y], 1)] = s.y;
        g_csr[atomicAdd(&g_cursor[d.z], 1)] = s.z;
        g_csr[atomicAdd(&g_cursor[d.w], 1)] = s.w;
    }
}

// ---------------- layer 1: x[N,8] -> g_hA[N,32] -----------------------------
__global__ void __launch_bounds__(256) k_layer1(const float* __restrict__ x,
                                                const float* __restrict__ Wl,
                                                const float* __restrict__ bl,
                                                const float* __restrict__ Wr) {
    __shared__ float Wls[DIN * H], Wrs[DIN * H], bls[H];
    for (int i = threadIdx.x; i < DIN * H; i += blockDim.x) {
        Wls[i] = Wl[i];
        Wrs[i] = Wr[i];
    }
    if (threadIdx.x < H) bls[threadIdx.x] = bl[threadIdx.x];
    __syncthreads();

    int n    = (blockIdx.x * blockDim.x + threadIdx.x) >> 5;
    int lane = threadIdx.x & 31;
    if (n >= N_NODES) return;

    int base = g_offsets[n];
    int cnt  = g_counts[n];

    // 16 edges per iteration: lane = sub*2 + q ; q selects float4 half of 8-dim row
    int sub = lane >> 1, q = lane & 1;
    const float4* x4 = (const float4*)x;
    float4 acc = make_float4(0.f, 0.f, 0.f, 0.f);
    int s0 = (sub < cnt) ? g_csr[base + sub] : -1;
    for (int i = 0; i < cnt; i += 16) {
        int en = i + 16 + sub;
        int sn = (en < cnt) ? g_csr[base + en] : -1;
        if (s0 >= 0) {
            float4 v = x4[s0 * 2 + q];
            acc.x += v.x; acc.y += v.y; acc.z += v.z; acc.w += v.w;
        }
        s0 = sn;
    }
    // reduce over sub (lane bits 1..4)
#pragma unroll
    for (int off = 16; off >= 2; off >>= 1) {
        acc.x += __shfl_down_sync(FULL, acc.x, off);
        acc.y += __shfl_down_sync(FULL, acc.y, off);
        acc.z += __shfl_down_sync(FULL, acc.z, off);
        acc.w += __shfl_down_sync(FULL, acc.w, off);
    }
    // lanes 0..1 hold totals for dims q*4 .. q*4+3
    __shared__ float4 msm4[8][2];
    __shared__ float  xsm[8][8];
    int w = (threadIdx.x >> 5);
    float inv = 1.f / fmaxf((float)cnt, 1.f);
    if (lane < 2) {
        msm4[w][lane] = make_float4(acc.x * inv, acc.y * inv, acc.z * inv, acc.w * inv);
    }
    if (lane < 8) xsm[w][lane] = x[n * DIN + lane];
    __syncwarp();

    const float* ms = (const float*)msm4[w];
    float o = bls[lane];
#pragma unroll
    for (int k = 0; k < DIN; k++) {
        o += ms[k] * Wls[k * H + lane] + xsm[w][k] * Wrs[k * H + lane];
    }
    g_hA[n * H + lane] = fmaxf(o, 0.f);
}

// ---------------- generic SAGE layer (32->32) gather+matmul -----------------
// hin row viewed as 8 float4; lane = sub*8+q processes edge slot sub, dims q*4..q*4+3
__device__ __forceinline__ float sage32(const float* __restrict__ hin,
                                        int n, int lane, int w,
                                        const float* __restrict__ wlT,
                                        const float* __restrict__ wrT,
                                        const float* __restrict__ bls,
                                        float4 (*ms4)[8], float4 (*hs4)[8]) {
    int base = g_offsets[n];
    int cnt  = g_counts[n];
    int sub = lane >> 3, q = lane & 7;
    const float4* h4 = (const float4*)hin;

    float4 acc = make_float4(0.f, 0.f, 0.f, 0.f);
    int s0 = (sub < cnt) ? g_csr[base + sub] : -1;
    for (int i = 0; i < cnt; i += 4) {
        int en = i + 4 + sub;
        int sn = (en < cnt) ? g_csr[base + en] : -1;
        if (s0 >= 0) {
            float4 v = h4[s0 * 8 + q];
            acc.x += v.x; acc.y += v.y; acc.z += v.z; acc.w += v.w;
        }
        s0 = sn;
    }
    // reduce over sub (lane bits 3,4)
#pragma unroll
    for (int off = 16; off >= 8; off >>= 1) {
        acc.x += __shfl_down_sync(FULL, acc.x, off);
        acc.y += __shfl_down_sync(FULL, acc.y, off);
        acc.z += __shfl_down_sync(FULL, acc.z, off);
        acc.w += __shfl_down_sync(FULL, acc.w, off);
    }
    float inv = 1.f / fmaxf((float)cnt, 1.f);
    if (lane < 8) {
        ms4[w][lane] = make_float4(acc.x * inv, acc.y * inv, acc.z * inv, acc.w * inv);
    }
    float hv = hin[n * H + lane];
    ((float*)hs4[w])[lane] = hv;
    __syncwarp();

    const float4* wl4 = (const float4*)(wlT + lane * WPAD);
    const float4* wr4 = (const float4*)(wrT + lane * WPAD);
    float o = bls[lane];
#pragma unroll
    for (int kk = 0; kk < 8; kk++) {
        float4 m4 = ms4[w][kk];
        float4 v4 = hs4[w][kk];
        float4 a4 = wl4[kk];
        float4 b4 = wr4[kk];
        o += m4.x * a4.x + m4.y * a4.y + m4.z * a4.z + m4.w * a4.w;
        o += v4.x * b4.x + v4.y * b4.y + v4.z * b4.z + v4.w * b4.w;
    }
    return o;
}

// ---------------- layer 2: g_hA -> g_hB --------------------------------------
__global__ void __launch_bounds__(256) k_layer2(const float* __restrict__ Wl,
                                                const float* __restrict__ bl,
                                                const float* __restrict__ Wr) {
    __shared__ float wlT[H * WPAD], wrT[H * WPAD], bls[H];
    __shared__ float4 ms4[8][8], hs4[8][8];
    for (int i = threadIdx.x; i < H * H; i += blockDim.x) {
        int k = i >> 5, c = i & 31;
        wlT[c * WPAD + k] = Wl[i];
        wrT[c * WPAD + k] = Wr[i];
    }
    if (threadIdx.x < H) bls[threadIdx.x] = bl[threadIdx.x];
    __syncthreads();

    int n    = (blockIdx.x * blockDim.x + threadIdx.x) >> 5;
    int lane = threadIdx.x & 31;
    if (n >= N_NODES) return;
    int w = threadIdx.x >> 5;

    float o = sage32(g_hA, n, lane, w, wlT, wrT, bls, ms4, hs4);
    g_hB[n * H + lane] = fmaxf(o, 0.f);
}

// ---------------- layer 3 + MLP head: g_hB -> out[N,3] -----------------------
__global__ void __launch_bounds__(256) k_layer3_head(float* __restrict__ out,
                                                     const float* __restrict__ Wl,
                                                     const float* __restrict__ bl,
                                                     const float* __restrict__ Wr,
                                                     const float* __restrict__ Wh1,
                                                     const float* __restrict__ bh1,
                                                     const float* __restrict__ Wh2,
                                                     const float* __restrict__ bh2) {
    __shared__ float wlT[H * WPAD], wrT[H * WPAD], w1T[H * WPAD];
    __shared__ float bls[H], b1s[H], W2s[H * 3], b2s[3];
    __shared__ float4 ms4[8][8], hs4[8][8];
    for (int i = threadIdx.x; i < H * H; i += blockDim.x) {
        int k = i >> 5, c = i & 31;
        wlT[c * WPAD + k] = Wl[i];
        wrT[c * WPAD + k] = Wr[i];
        w1T[c * WPAD + k] = Wh1[i];
    }
    if (threadIdx.x < H) {
        bls[threadIdx.x] = bl[threadIdx.x];
        b1s[threadIdx.x] = bh1[threadIdx.x];
    }
    for (int i = threadIdx.x; i < H * 3; i += blockDim.x) W2s[i] = Wh2[i];
    if (threadIdx.x < 3) b2s[threadIdx.x] = bh2[threadIdx.x];
    __syncthreads();

    int n    = (blockIdx.x * blockDim.x + threadIdx.x) >> 5;
    int lane = threadIdx.x & 31;
    if (n >= N_NODES) return;
    int w = threadIdx.x >> 5;

    float o = sage32(g_hB, n, lane, w, wlT, wrT, bls, ms4, hs4);
    float h3 = fmaxf(o, 0.f);

    // head layer 1: 32 -> 32, relu. reuse hs4 as broadcast buffer for h3
    __syncwarp();
    ((float*)hs4[w])[lane] = h3;
    __syncwarp();
    const float4* w14 = (const float4*)(w1T + lane * WPAD);
    float t1 = b1s[lane];
#pragma unroll
    for (int kk = 0; kk < 8; kk++) {
        float4 v4 = hs4[w][kk];
        float4 a4 = w14[kk];
        t1 += v4.x * a4.x + v4.y * a4.y + v4.z * a4.z + v4.w * a4.w;
    }
    t1 = fmaxf(t1, 0.f);

    // head layer 2: 32 -> 3, warp reduction
    float p0 = t1 * W2s[lane * 3 + 0];
    float p1 = t1 * W2s[lane * 3 + 1];
    float p2 = t1 * W2s[lane * 3 + 2];
#pragma unroll
    for (int off = 16; off > 0; off >>= 1) {
        p0 += __shfl_xor_sync(FULL, p0, off);
        p1 += __shfl_xor_sync(FULL, p1, off);
        p2 += __shfl_xor_sync(FULL, p2, off);
    }
    if (lane == 0) {
        out[n * 3 + 0] = p0 + b2s[0];
        out[n * 3 + 1] = p1 + b2s[1];
        out[n * 3 + 2] = p2 + b2s[2];
    }
}

// ---------------- launcher ---------------------------------------------------
extern "C" void kernel_launch(void* const* d_in, const int* in_sizes, int n_in,
                              void* d_out, int out_size) {
    const float* x   = (const float*)d_in[0];
    const int*   ei  = (const int*)d_in[1];    // int64 in reference -> int32 on device
    const int*   src = ei;
    const int*   dst = ei + N_EDGES;
    const float* Wl1 = (const float*)d_in[2];
    const float* bl1 = (const float*)d_in[3];
    const float* Wr1 = (const float*)d_in[4];
    const float* Wl2 = (const float*)d_in[5];
    const float* bl2 = (const float*)d_in[6];
    const float* Wr2 = (const float*)d_in[7];
    const float* Wl3 = (const float*)d_in[8];
    const float* bl3 = (const float*)d_in[9];
    const float* Wr3 = (const float*)d_in[10];
    const float* Wh1 = (const float*)d_in[11];
    const float* bh1 = (const float*)d_in[12];
    const float* Wh2 = (const float*)d_in[13];
    const float* bh2 = (const float*)d_in[14];
    float* out = (float*)d_out;

    int nblk = (N_NODES + SCAN_CHUNK - 1) / SCAN_CHUNK;

    k_zero_counts<<<(N_NODES / 4 + 255) / 256, 256>>>();
    k_hist<<<(N_EDGES / 4 + 255) / 256, 256>>>(dst);
    k_scan1<<<nblk, SCAN_CHUNK>>>();
    k_scan2<<<1, 256>>>(nblk);
    k_scan3<<<(N_NODES + 255) / 256, 256>>>();
    k_fill<<<(N_EDGES / 4 + 255) / 256, 256>>>(src, dst);

    int node_blocks = (N_NODES + 7) / 8;  // 8 warps (nodes) per 256-thread block
    k_layer1<<<node_blocks, 256>>>(x, Wl1, bl1, Wr1);
    k_layer2<<<node_blocks, 256>>>(Wl2, bl2, Wr2);
    k_layer3_head<<<node_blocks, 256>>>(out, Wl3, bl3, Wr3, Wh1, bh1, Wh2, bh2);
}